// round 17
// baseline (speedup 1.0000x reference)
#include <cuda_runtime.h>
#include <math.h>
#include <stddef.h>
#include <stdint.h>

#define NN   20000
#define EE   320000
#define DD   128
#define MOx  128
#define MINK 257
#define NCAT 512      // Wm1(256) || Wx1(256)
#define MT_N 157      // ceil(20000/128)
#define NPAD (MT_N*128)

// ---------------- scratch (device globals; no runtime allocation) ----------------
__device__ __align__(16) float g_U[(size_t)NN * NCAT];
__device__ __align__(16) float g_V[(size_t)NN * NCAT];
__device__ __align__(16) float g_diff[EE * 3];
__device__ __align__(16) float g_d2[EE];
__device__              float g_sum;
__device__ __align__(16) float g_agg[NN * MOx];
__device__ __align__(16) float g_T[(size_t)NPAD * 256];
__device__ __align__(16) float g_hbuf[NN * DD];
__device__ __align__(16) float g_xbuf[NN * 3];
__device__ __align__(16) float g_Wcat[MINK * NCAT];
__device__ __align__(16) float g_bcat[NCAT];
__device__ __align__(16) uint32_t g_Wm2T[128 * 256];          // Wm2^T tf32 [n][k]
__device__ __align__(16) uint32_t g_WcatT[2 * 512 * 128];     // Wcat^T tf32 [s][n][k]
__device__ __align__(16) uint32_t g_Wh1T[256 * 256];          // Wh1^T tf32 [n][k]
__device__ __align__(16) uint32_t g_Wh2T[128 * 256];          // Wh2^T tf32 [n][k]

__device__ __forceinline__ float siluf(float z) { return z / (1.f + expf(-z)); }
__device__ __forceinline__ float sigmf(float z) { return 1.f / (1.f + expf(-z)); }
__device__ __forceinline__ uint32_t tf32r(float x) {
  uint32_t r; asm("cvt.rna.tf32.f32 %0, %1;" : "=r"(r) : "f"(x)); return r;
}
__device__ __forceinline__ void red2(float* p, float v0, float v1) {
  asm volatile("red.global.add.v2.f32 [%0], {%1, %2};" :: "l"(p), "f"(v0), "f"(v1) : "memory");
}

__device__ __forceinline__ void mma16n8k8(float c[4], uint32_t a0, uint32_t a1,
                                          uint32_t a2, uint32_t a3,
                                          uint32_t b0, uint32_t b1) {
  asm volatile(
      "mma.sync.aligned.m16n8k8.row.col.f32.tf32.tf32.f32 "
      "{%0,%1,%2,%3}, {%4,%5,%6,%7}, {%8,%9}, {%0,%1,%2,%3};"
      : "+f"(c[0]), "+f"(c[1]), "+f"(c[2]), "+f"(c[3])
      : "r"(a0), "r"(a1), "r"(a2), "r"(a3), "r"(b0), "r"(b1));
}

#define SAS 36   // padded k-stride (uint32) -> conflict-free fragment loads

// shared MMA inner loop: sA rows = M(128), sB rows = N(128), 32 k per call
__device__ __forceinline__ void mma_chunk(const uint32_t* sA, const uint32_t* sB,
                                          float acc[16][4], int mrow, int gID, int tg) {
#pragma unroll
  for (int ks = 0; ks < 4; ++ks) {
    const int kk = ks * 8;
    const uint32_t a0 = sA[(mrow + gID) * SAS + kk + tg];
    const uint32_t a1 = sA[(mrow + gID + 8) * SAS + kk + tg];
    const uint32_t a2 = sA[(mrow + gID) * SAS + kk + tg + 4];
    const uint32_t a3 = sA[(mrow + gID + 8) * SAS + kk + tg + 4];
#pragma unroll
    for (int nn = 0; nn < 16; ++nn) {
      const int n0 = nn * 8 + gID;
      const uint32_t b0 = sB[n0 * SAS + kk + tg];
      const uint32_t b1 = sB[n0 * SAS + kk + tg + 4];
      mma16n8k8(acc[nn], a0, a1, a2, a3, b0, b1);
    }
  }
}

// ---------------- small setup kernels ----------------
__global__ void k_pack(const float* __restrict__ Wm1, const float* __restrict__ Wx1,
                       const float* __restrict__ bm1, const float* __restrict__ bx1, int l) {
  int i = blockIdx.x * 256 + threadIdx.x;
  int k = i / NCAT, n = i - k * NCAT;
  g_Wcat[i] = (n < 256) ? Wm1[((size_t)l * MINK + k) * 256 + n]
                        : Wx1[((size_t)l * MINK + k) * 256 + (n - 256)];
  if (i < NCAT) g_bcat[i] = (i < 256) ? bm1[l * 256 + i] : bx1[l * 256 + (i - 256)];
}

__global__ void k_packB(const float* __restrict__ Wm2, int l) {
  int i = blockIdx.x * 256 + threadIdx.x;                         // i = n*256 + k
  int n = i >> 8, k = i & 255;
  g_Wm2T[i] = tf32r(Wm2[(size_t)l * 32768 + k * 128 + n]);
}

__global__ void k_packW() {                        // Wcat^T tf32 (for k_uvt), 512 blocks
  int i = blockIdx.x * 256 + threadIdx.x;          // i = s*65536 + n*128 + k
  int s = i >> 16;
  int n = (i >> 7) & 511;
  int k = i & 127;
  g_WcatT[i] = tf32r(g_Wcat[(size_t)(s * 128 + k) * NCAT + n]);
}

__global__ void k_packH(const float* __restrict__ Wh1, const float* __restrict__ Wh2, int l) {
  int i = blockIdx.x * 256 + threadIdx.x;          // 384 blocks
  if (i < 65536) {                                 // Wh1^T: n(256) x k(256)
    int n = i >> 8, k = i & 255;
    g_Wh1T[i] = tf32r(Wh1[(size_t)l * 65536 + k * 256 + n]);
  } else {                                         // Wh2^T: n(128) x k(256)
    int j = i - 65536;
    int n = j >> 8, k = j & 255;
    g_Wh2T[j] = tf32r(Wh2[(size_t)l * 32768 + k * 128 + n]);
  }
}

__global__ void k_zero() {
  int i = blockIdx.x * 256 + threadIdx.x;
  g_agg[i] = 0.f;
  if (i == 0) g_sum = 0.f;
}

__global__ void k_copyx(const float* __restrict__ x_ext, float* __restrict__ xout_ext, int layer) {
  int i = blockIdx.x * 256 + threadIdx.x;
  if (i >= NN * 3) return;
  const float* xin = (layer == 0) ? x_ext : g_xbuf;
  float* xo = (layer == 1) ? xout_ext : g_xbuf;
  xo[i] = xin[i];
}

__global__ void k_edge(const int* __restrict__ ei, const float* __restrict__ x_ext, int layer) {
  const float* x = (layer == 0) ? x_ext : g_xbuf;
  int e = blockIdx.x * 256 + threadIdx.x;
  int s = ei[e], d = ei[EE + e];
  float dx = x[s * 3 + 0] - x[d * 3 + 0];
  float dy = x[s * 3 + 1] - x[d * 3 + 1];
  float dz = x[s * 3 + 2] - x[d * 3 + 2];
  g_diff[e * 3 + 0] = dx; g_diff[e * 3 + 1] = dy; g_diff[e * 3 + 2] = dz;
  float d2 = dx * dx + dy * dy + dz * dz;
  g_d2[e] = d2;
#pragma unroll
  for (int off = 16; off >= 1; off >>= 1) d2 += __shfl_xor_sync(0xffffffffu, d2, off);
  __shared__ float ws[8];
  if ((threadIdx.x & 31) == 0) ws[threadIdx.x >> 5] = d2;
  __syncthreads();
  if (threadIdx.x < 8) {
    float v = ws[threadIdx.x];
#pragma unroll
    for (int off = 4; off >= 1; off >>= 1) v += __shfl_xor_sync(0x000000ffu, v, off);
    if (threadIdx.x == 0) atomicAdd(&g_sum, v);
  }
}

// ---------------- node GEMM via tf32 MMA: U,V [N,512] ----------------
__global__ __launch_bounds__(256) void k_uvt(const float* __restrict__ h_ext, int layer) {
  const float* __restrict__ hin = (layer == 0) ? h_ext : g_hbuf;
  __shared__ __align__(16) uint32_t sA[128 * SAS];
  __shared__ __align__(16) uint32_t sB[128 * SAS];
  const int mt = blockIdx.x, nt = blockIdx.y;      // nt 0..7: 0-3 U, 4-7 V
  const int sel = (nt >= 4) ? 1 : 0;
  const int c0 = (nt & 3) * 128;
  float* __restrict__ out = sel ? g_V : g_U;
  const uint32_t* __restrict__ Bsrc = g_WcatT + (size_t)sel * 65536 + (size_t)c0 * 128;

  const int tid = threadIdx.x;
  const int wid = tid >> 5, lane = tid & 31;
  const int rowBase = mt * 128;
  const int arow = tid >> 1;
  const int khalf = (tid & 1) * 16;
  const int row = rowBase + arow;
  const bool valid = row < NN;
  const float* hp = hin + (size_t)row * DD;

  const int gID = lane >> 2;
  const int tg  = lane & 3;
  const int mrow = wid * 16;

  float acc[16][4];
#pragma unroll
  for (int nt2 = 0; nt2 < 16; ++nt2)
#pragma unroll
    for (int j = 0; j < 4; ++j) acc[nt2][j] = 0.f;

  for (int kc = 0; kc < 4; ++kc) {
    const int k0 = kc * 32;
#pragma unroll
    for (int g = 0; g < 4; ++g) {
      const int kk = k0 + khalf + g * 4;
      float4 a = make_float4(0.f, 0.f, 0.f, 0.f);
      if (valid) a = *(const float4*)(hp + kk);
      uint4 av;
      av.x = tf32r(a.x); av.y = tf32r(a.y); av.z = tf32r(a.z); av.w = tf32r(a.w);
      *(uint4*)&sA[arow * SAS + khalf + g * 4] = av;
      *(uint4*)&sB[arow * SAS + khalf + g * 4] = *(const uint4*)(Bsrc + arow * 128 + kk);
    }
    __syncthreads();
    mma_chunk(sA, sB, acc, mrow, gID, tg);
    __syncthreads();
  }

  const int rA = rowBase + mrow + gID;
  const int rB = rA + 8;
#pragma unroll
  for (int nn = 0; nn < 16; ++nn) {
    const int col = c0 + nn * 8 + tg * 2;
    if (rA < NN) *(float2*)&out[(size_t)rA * NCAT + col] = make_float2(acc[nn][0], acc[nn][1]);
    if (rB < NN) *(float2*)&out[(size_t)rB * NCAT + col] = make_float2(acc[nn][2], acc[nn][3]);
  }
}

// ---------------- tf32 warp-MMA GEMM2, register-pipelined gather ----------------
__global__ __launch_bounds__(256) void k_gemm2w(const int* __restrict__ ei,
                                                const float* __restrict__ bm2,
                                                const float* __restrict__ Wa,
                                                const float* __restrict__ ba, int l) {
  __shared__ __align__(16) uint32_t sA[128 * SAS];
  __shared__ __align__(16) uint32_t sB[128 * SAS];
  __shared__ float s_wa[128], s_b2[128], s_d2s[128];
  __shared__ __align__(16) float s_w[256], s_bc[256];
  __shared__ int s_src[128], s_dst[128];

  const int tid = threadIdx.x;
  const int wid = tid >> 5, lane = tid & 31;
  const int rowBase = blockIdx.x * 128;

  if (tid < 128) {
    const int e = rowBase + tid;
    s_src[tid] = ei[e];
    s_dst[tid] = ei[EE + e];
    s_d2s[tid] = g_d2[e];
    s_wa[tid] = Wa[l * 128 + tid];
    s_b2[tid] = bm2[l * 128 + tid];
  }
  s_w[tid]  = g_Wcat[(size_t)256 * NCAT + tid];
  s_bc[tid] = g_bcat[tid];
  __syncthreads();

  const int arow = tid >> 1;
  const int khalf = (tid & 1) * 16;
  const int src = s_src[arow], dst = s_dst[arow];
  const float d2v = s_d2s[arow];
  const float* up0 = g_U + (size_t)src * NCAT;
  const float* vp0 = g_V + (size_t)dst * NCAT;

  const int gID = lane >> 2;
  const int tg  = lane & 3;
  const int mrow = wid * 16;

  float acc[16][4];
#pragma unroll
  for (int nt = 0; nt < 16; ++nt)
#pragma unroll
    for (int j = 0; j < 4; ++j) acc[nt][j] = 0.f;

  // prologue: load chunk 0 u/v
  float4 cu[4], cv[4];
#pragma unroll
  for (int g = 0; g < 4; ++g) {
    cu[g] = *(const float4*)(up0 + khalf + g * 4);
    cv[g] = *(const float4*)(vp0 + khalf + g * 4);
  }

#pragma unroll
  for (int kc = 0; kc < 8; ++kc) {
    const int k0 = kc * 32;
    // stage B chunk (L2-hot)
    uint4 bs[4];
#pragma unroll
    for (int g = 0; g < 4; ++g)
      bs[g] = *(const uint4*)(g_Wm2T + arow * 256 + k0 + khalf + g * 4);
    // transform current u/v -> sA
#pragma unroll
    for (int g = 0; g < 4; ++g) {
      const int kk = k0 + khalf + g * 4;
      const float4 w = *(const float4*)&s_w[kk];
      const float4 b = *(const float4*)&s_bc[kk];
      uint4 av;
      av.x = tf32r(siluf(fmaf(d2v, w.x, cu[g].x + cv[g].x + b.x)));
      av.y = tf32r(siluf(fmaf(d2v, w.y, cu[g].y + cv[g].y + b.y)));
      av.z = tf32r(siluf(fmaf(d2v, w.z, cu[g].z + cv[g].z + b.z)));
      av.w = tf32r(siluf(fmaf(d2v, w.w, cu[g].w + cv[g].w + b.w)));
      *(uint4*)&sA[arow * SAS + khalf + g * 4] = av;
      *(uint4*)&sB[arow * SAS + khalf + g * 4] = bs[g];
    }
    // prefetch next chunk's u/v — latency hides behind sync + MMA
    if (kc < 7) {
      const int nb = (kc + 1) * 32 + khalf;
#pragma unroll
      for (int g = 0; g < 4; ++g) {
        cu[g] = *(const float4*)(up0 + nb + g * 4);
        cv[g] = *(const float4*)(vp0 + nb + g * 4);
      }
    }
    __syncthreads();
    mma_chunk(sA, sB, acc, mrow, gID, tg);
    __syncthreads();
  }

  // epilogue: bias, gate dot, v2-scatter
  const int rA = mrow + gID;
  const int rB = rA + 8;
  float dotA = 0.f, dotB = 0.f;
#pragma unroll
  for (int nt = 0; nt < 16; ++nt) {
#pragma unroll
    for (int j = 0; j < 2; ++j) {
      const int col = nt * 8 + tg * 2 + j;
      const float bb = s_b2[col], wv = s_wa[col];
      acc[nt][j]     += bb;
      acc[nt][2 + j] += bb;
      dotA = fmaf(acc[nt][j],     wv, dotA);
      dotB = fmaf(acc[nt][2 + j], wv, dotB);
    }
  }
  dotA += __shfl_xor_sync(0xffffffffu, dotA, 1);
  dotA += __shfl_xor_sync(0xffffffffu, dotA, 2);
  dotB += __shfl_xor_sync(0xffffffffu, dotB, 1);
  dotB += __shfl_xor_sync(0xffffffffu, dotB, 2);
  const float bav = ba[l];
  const float sgA = sigmf(dotA + bav);
  const float sgB = sigmf(dotB + bav);
  float* pA = g_agg + (size_t)s_src[rA] * MOx;
  float* pB = g_agg + (size_t)s_src[rB] * MOx;
#pragma unroll
  for (int nt = 0; nt < 16; ++nt) {
    const int col = nt * 8 + tg * 2;
    red2(pA + col, acc[nt][0] * sgA, acc[nt][1] * sgA);
    red2(pB + col, acc[nt][2] * sgB, acc[nt][3] * sgB);
  }
}

// ---------------- fused x-message ----------------
__global__ __launch_bounds__(256) void k_mxf(const int* __restrict__ ei,
                                             const float* __restrict__ Wx2,
                                             const float* __restrict__ bx2,
                                             float* __restrict__ xout_ext, int layer) {
  __shared__ float sW[768];
#pragma unroll
  for (int i = threadIdx.x; i < 768; i += 256) sW[i] = Wx2[(size_t)layer * 768 + i];
  __syncthreads();
  const int gw = blockIdx.x * 8 + (threadIdx.x >> 5);
  const int lane = threadIdx.x & 31;
  const int s = ei[gw], d = ei[EE + gw];
  const float d2v = g_d2[gw];
  const float* up = g_U + (size_t)s * NCAT + 256 + lane * 8;
  const float* vp = g_V + (size_t)d * NCAT + 256 + lane * 8;
  const float* wp = g_Wcat + (size_t)256 * NCAT + 256 + lane * 8;
  const float* bp = g_bcat + 256 + lane * 8;
  float u[8], v[8], w[8], bc[8];
  *(float4*)&u[0] = *(const float4*)up;   *(float4*)&u[4] = *(const float4*)(up + 4);
  *(float4*)&v[0] = *(const float4*)vp;   *(float4*)&v[4] = *(const float4*)(vp + 4);
  *(float4*)&w[0] = *(const float4*)wp;   *(float4*)&w[4] = *(const float4*)(wp + 4);
  *(float4*)&bc[0] = *(const float4*)bp;  *(float4*)&bc[4] = *(const float4*)(bp + 4);
  float a0 = 0.f, a1 = 0.f, a2 = 0.f;
#pragma unroll
  for (int j = 0; j < 8; ++j) {
    const float c = siluf(fmaf(d2v, w[j], u[j] + v[j] + bc[j]));
    const int kk = lane * 8 + j;
    a0 = fmaf(c, sW[kk * 3 + 0], a0);
    a1 = fmaf(c, sW[kk * 3 + 1], a1);
    a2 = fmaf(c, sW[kk * 3 + 2], a2);
  }
#pragma unroll
  for (int off = 16; off >= 1; off >>= 1) {
    a0 += __shfl_xor_sync(0xffffffffu, a0, off);
    a1 += __shfl_xor_sync(0xffffffffu, a1, off);
    a2 += __shfl_xor_sync(0xffffffffu, a2, off);
  }
  if (lane == 0) {
    const float inv = 1.f / (sqrtf(g_sum) + 1.f);
    const float m0 = a0 + bx2[layer * 3 + 0];
    const float m1 = a1 + bx2[layer * 3 + 1];
    const float m2 = a2 + bx2[layer * 3 + 2];
    float* xo = (layer == 1) ? xout_ext : g_xbuf;
    atomicAdd(&xo[(size_t)s * 3 + 0], g_diff[gw * 3 + 0] * m0 * inv);
    atomicAdd(&xo[(size_t)s * 3 + 1], g_diff[gw * 3 + 1] * m1 * inv);
    atomicAdd(&xo[(size_t)s * 3 + 2], g_diff[gw * 3 + 2] * m2 * inv);
  }
}

// ---------------- GEMM3 via tf32 MMA: T = silu(cat(h,agg)@Wh1+bh1) [N,256] ----------------
__global__ __launch_bounds__(256) void k_g3t(const float* __restrict__ h_ext,
                                             const float* __restrict__ bh1, int layer) {
  const float* __restrict__ hin = (layer == 0) ? h_ext : g_hbuf;
  __shared__ __align__(16) uint32_t sA[128 * SAS];
  __shared__ __align__(16) uint32_t sB[128 * SAS];
  __shared__ float s_b[128];
  const int mt = blockIdx.x;
  const int c0 = blockIdx.y * 128;
  const uint32_t* __restrict__ Bsrc = g_Wh1T + (size_t)c0 * 256;

  const int tid = threadIdx.x;
  const int wid = tid >> 5, lane = tid & 31;
  const int rowBase = mt * 128;
  const int arow = tid >> 1;
  const int khalf = (tid & 1) * 16;
  const int row = rowBase + arow;
  const bool valid = row < NN;
  if (tid < 128) s_b[tid] = bh1[(size_t)layer * 256 + c0 + tid];

  const int gID = lane >> 2;
  const int tg  = lane & 3;
  const int mrow = wid * 16;

  float acc[16][4];
#pragma unroll
  for (int nn = 0; nn < 16; ++nn)
#pragma unroll
    for (int j = 0; j < 4; ++j) acc[nn][j] = 0.f;

  for (int kc = 0; kc < 8; ++kc) {
    const int k0 = kc * 32;
#pragma unroll
    for (int g = 0; g < 4; ++g) {
      const int kk = k0 + khalf + g * 4;
      float4 a = make_float4(0.f, 0.f, 0.f, 0.f);
      if (valid) {
        const float* p = (kk < 128) ? hin + (size_t)row * DD + kk
                                    : g_agg + (size_t)row * MOx + (kk - 128);
        a = *(const float4*)p;
      }
      uint4 av;
      av.x = tf32r(a.x); av.y = tf32r(a.y); av.z = tf32r(a.z); av.w = tf32r(a.w);
      *(uint4*)&sA[arow * SAS + khalf + g * 4] = av;
      *(uint4*)&sB[arow * SAS + khalf + g * 4] = *(const uint4*)(Bsrc + arow * 256 + kk);
    }
    __syncthreads();
    mma_chunk(sA, sB, acc, mrow, gID, tg);
    __syncthreads();
  }

  const int rA = rowBase + mrow + gID;
  const int rB = rA + 8;
#pragma unroll
  for (int nn = 0; nn < 16; ++nn) {
    const int lc = nn * 8 + tg * 2;
    if (rA < NN)
      *(float2*)&g_T[(size_t)rA * 256 + c0 + lc] =
          make_float2(siluf(acc[nn][0] + s_b[lc]), siluf(acc[nn][1] + s_b[lc + 1]));
    if (rB < NN)
      *(float2*)&g_T[(size_t)rB * 256 + c0 + lc] =
          make_float2(siluf(acc[nn][2] + s_b[lc]), siluf(acc[nn][3] + s_b[lc + 1]));
  }
}

// ---------------- GEMM4 via tf32 MMA: h_new = T@Wh2+bh2 [N,128] ----------------
__global__ __launch_bounds__(256) void k_g4t(const float* __restrict__ bh2,
                                             float* __restrict__ hout_ext, int layer) {
  float* hout = (layer == 1) ? hout_ext : g_hbuf;
  __shared__ __align__(16) uint32_t sA[128 * SAS];
  __shared__ __align__(16) uint32_t sB[128 * SAS];
  __shared__ float s_b[128];
  const int mt = blockIdx.x;

  const int tid = threadIdx.x;
  const int wid = tid >> 5, lane = tid & 31;
  const int rowBase = mt * 128;
  const int arow = tid >> 1;
  const int khalf = (tid & 1) * 16;
  const int row = rowBase + arow;
  const bool valid = row < NN;
  if (tid < 128) s_b[tid] = bh2[(size_t)layer * 128 + tid];

  const int gID = lane >> 2;
  const int tg  = lane & 3;
  const int mrow = wid * 16;

  float acc[16][4];
#pragma unroll
  for (int nn = 0; nn < 16; ++nn)
#pragma unroll
    for (int j = 0; j < 4; ++j) acc[nn][j] = 0.f;

  for (int kc = 0; kc < 8; ++kc) {
    const int k0 = kc * 32;
#pragma unroll
    for (int g = 0; g < 4; ++g) {
      const int kk = k0 + khalf + g * 4;
      float4 a = make_float4(0.f, 0.f, 0.f, 0.f);
      if (valid) a = *(const float4*)(g_T + (size_t)row * 256 + kk);
      uint4 av;
      av.x = tf32r(a.x); av.y = tf32r(a.y); av.z = tf32r(a.z); av.w = tf32r(a.w);
      *(uint4*)&sA[arow * SAS + khalf + g * 4] = av;
      *(uint4*)&sB[arow * SAS + khalf + g * 4] = *(const uint4*)(g_Wh2T + arow * 256 + kk);
    }
    __syncthreads();
    mma_chunk(sA, sB, acc, mrow, gID, tg);
    __syncthreads();
  }

  const int rA = rowBase + mrow + gID;
  const int rB = rA + 8;
#pragma unroll
  for (int nn = 0; nn < 16; ++nn) {
    const int lc = nn * 8 + tg * 2;
    if (rA < NN)
      *(float2*)&hout[(size_t)rA * DD + lc] =
          make_float2(acc[nn][0] + s_b[lc], acc[nn][1] + s_b[lc + 1]);
    if (rB < NN)
      *(float2*)&hout[(size_t)rB * DD + lc] =
          make_float2(acc[nn][2] + s_b[lc], acc[nn][3] + s_b[lc + 1]);
  }
}

// ---------------- host ----------------
extern "C" void kernel_launch(void* const* d_in, const int* in_sizes, int n_in,
                              void* d_out, int out_size) {
  (void)in_sizes; (void)n_in; (void)out_size;
  const int*   ei  = (const int*)  d_in[0];
  const float* h0  = (const float*)d_in[1];
  const float* x0  = (const float*)d_in[2];
  const float* Wm1 = (const float*)d_in[3];
  const float* bm1 = (const float*)d_in[4];
  const float* Wm2 = (const float*)d_in[5];
  const float* bm2 = (const float*)d_in[6];
  const float* Wx1 = (const float*)d_in[7];
  const float* bx1 = (const float*)d_in[8];
  const float* Wx2 = (const float*)d_in[9];
  const float* bx2 = (const float*)d_in[10];
  const float* Wh1 = (const float*)d_in[11];
  const float* bh1 = (const float*)d_in[12];
  const float* Wh2 = (const float*)d_in[13];
  const float* bh2 = (const float*)d_in[14];
  const float* Wa  = (const float*)d_in[15];
  const float* ba  = (const float*)d_in[16];

  float* out  = (float*)d_out;
  float* xout = out + (size_t)NN * DD;   // output layout: [h (N*128) ; x (N*3)]

  for (int l = 0; l < 2; ++l) {
    k_pack <<<(MINK * NCAT) / 256, 256>>>(Wm1, Wx1, bm1, bx1, l);
    k_packB<<<128, 256>>>(Wm2, l);
    k_packW<<<512, 256>>>();
    k_packH<<<384, 256>>>(Wh1, Wh2, l);
    k_zero <<<(NN * MOx) / 256, 256>>>();
    k_copyx<<<(NN * 3 + 255) / 256, 256>>>(x0, xout, l);
    k_edge <<<EE / 256, 256>>>(ei, x0, l);
    {
      dim3 g(MT_N, 8);
      k_uvt<<<g, 256>>>(h0, l);
    }
    k_gemm2w<<<2500, 256>>>(ei, bm2, Wa, ba, l);
    k_mxf  <<<EE / 8, 256>>>(ei, Wx2, bx2, xout, l);
    {
      dim3 g(MT_N, 2);
      k_g3t<<<g, 256>>>(h0, bh1, l);
    }
    k_g4t<<<MT_N, 256>>>(bh2, out, l);
  }
}